// round 1
// baseline (speedup 1.0000x reference)
#include <cuda_runtime.h>

// Problem constants (fixed shapes from reference)
#define B_ 4
#define T_ 160
#define U_ 80
#define DE 640
#define HH 640    // inner
#define VV 1024   // vocab
#define TU (T_ * U_)   // 12800

// Scratch for projections (allocation-free rule: __device__ globals)
__device__ float g_proj_e[B_ * T_ * HH];   // (b*T + t, h)
__device__ float g_proj_d[B_ * U_ * HH];   // (b*U + u, h), b1 folded in

__device__ __forceinline__ float fast_tanh(float x) {
    // tanh(x) = 1 - 2/(exp(2x)+1); ex2/rcp approx are ~1e-7 rel err -> safe
    float e;
    asm("ex2.approx.f32 %0, %1;" : "=f"(e) : "f"(x * 2.885390081777927f)); // 2*log2(e)
    float r;
    asm("rcp.approx.f32 %0, %1;" : "=f"(r) : "f"(e + 1.0f));
    return fmaf(-2.0f, r, 1.0f);
}

// ---------------------------------------------------------------------------
// Stage 1: C[M,640] = A[M,640] @ W[640,640] (+ bias). W row stride = HH.
// BM=64, BN=64, BK=16, 256 threads, 4x4 register tile.
// ---------------------------------------------------------------------------
__global__ void proj_kernel(const float* __restrict__ A,
                            const float* __restrict__ W,
                            const float* __restrict__ bias,
                            float* __restrict__ C)
{
    __shared__ float As[16][65];
    __shared__ float Bs[16][64];

    const int ltid = threadIdx.x;
    const int m0 = blockIdx.y * 64;
    const int n0 = blockIdx.x * 64;

    const int arow = ltid >> 2;          // 0..63
    const int ak4  = (ltid & 3) * 4;     // 0,4,8,12
    const int bk   = ltid >> 4;          // 0..15
    const int bn   = (ltid & 15) * 4;    // 0..60

    const int tx = ltid & 15;            // col group (TN=4)
    const int ty = ltid >> 4;            // row group (TM=4)

    float acc[4][4] = {};

    for (int k0 = 0; k0 < DE; k0 += 16) {
        float4 av = *(const float4*)&A[(size_t)(m0 + arow) * DE + k0 + ak4];
        As[ak4 + 0][arow] = av.x;
        As[ak4 + 1][arow] = av.y;
        As[ak4 + 2][arow] = av.z;
        As[ak4 + 3][arow] = av.w;

        *(float4*)&Bs[bk][bn] = *(const float4*)&W[(size_t)(k0 + bk) * HH + n0 + bn];

        __syncthreads();

        #pragma unroll
        for (int k = 0; k < 16; k++) {
            float a[4], b[4];
            #pragma unroll
            for (int j = 0; j < 4; j++) a[j] = As[k][ty * 4 + j];
            #pragma unroll
            for (int i = 0; i < 4; i++) b[i] = Bs[k][tx * 4 + i];
            #pragma unroll
            for (int j = 0; j < 4; j++)
                #pragma unroll
                for (int i = 0; i < 4; i++)
                    acc[j][i] = fmaf(a[j], b[i], acc[j][i]);
        }
        __syncthreads();
    }

    #pragma unroll
    for (int j = 0; j < 4; j++) {
        const int row = m0 + ty * 4 + j;
        #pragma unroll
        for (int i = 0; i < 4; i++) {
            float v = acc[j][i];
            if (bias) v += bias[n0 + tx * 4 + i];
            C[(size_t)row * HH + n0 + tx * 4 + i] = v;
        }
    }
}

// ---------------------------------------------------------------------------
// Stage 2: fused joint GEMM.
// C[b, r, v] = tanh(proj_e[b, r/U, :] + proj_d[b, r%U, :]) @ W2 + b2
// BM=64, BN=128, BK=16, 256 threads, 4x8 register tile.
// ---------------------------------------------------------------------------
__global__ void joint_kernel(const float* __restrict__ W2,
                             const float* __restrict__ b2,
                             float* __restrict__ out)
{
    __shared__ float As[16][65];
    __shared__ float Bs[16][128];

    const int ltid = threadIdx.x;
    const int b  = blockIdx.z;
    const int m0 = blockIdx.y * 64;      // row within batch, 0..12736
    const int n0 = blockIdx.x * 128;

    // A-tile loader: each thread owns one (row, k4) slot, fixed across k-loop
    const int arow = ltid >> 2;          // 0..63
    const int ak4  = (ltid & 3) * 4;     // 0,4,8,12
    const int r    = m0 + arow;
    const float* __restrict__ pe = &g_proj_e[(size_t)(b * T_ + r / U_) * HH];
    const float* __restrict__ pd = &g_proj_d[(size_t)(b * U_ + r % U_) * HH];

    // B-tile loader: 16x128 floats = 32 float4/row, 2 rows per thread
    const int bk = ltid >> 5;            // 0..7  (+8 for second)
    const int bn = (ltid & 31) * 4;      // 0..124

    const int tx = ltid & 15;            // col group (TN=8)
    const int ty = ltid >> 4;            // row group (TM=4)

    float acc[4][8] = {};

    for (int k0 = 0; k0 < HH; k0 += 16) {
        float4 ev = *(const float4*)&pe[k0 + ak4];
        float4 dv = *(const float4*)&pd[k0 + ak4];
        As[ak4 + 0][arow] = fast_tanh(ev.x + dv.x);
        As[ak4 + 1][arow] = fast_tanh(ev.y + dv.y);
        As[ak4 + 2][arow] = fast_tanh(ev.z + dv.z);
        As[ak4 + 3][arow] = fast_tanh(ev.w + dv.w);

        #pragma unroll
        for (int t = 0; t < 2; t++) {
            *(float4*)&Bs[bk + t * 8][bn] =
                *(const float4*)&W2[(size_t)(k0 + bk + t * 8) * VV + n0 + bn];
        }

        __syncthreads();

        #pragma unroll
        for (int k = 0; k < 16; k++) {
            float a[4];
            #pragma unroll
            for (int j = 0; j < 4; j++) a[j] = As[k][ty * 4 + j];
            float4 bv0 = *(float4*)&Bs[k][tx * 8];
            float4 bv1 = *(float4*)&Bs[k][tx * 8 + 4];
            float bb[8] = {bv0.x, bv0.y, bv0.z, bv0.w, bv1.x, bv1.y, bv1.z, bv1.w};
            #pragma unroll
            for (int j = 0; j < 4; j++)
                #pragma unroll
                for (int i = 0; i < 8; i++)
                    acc[j][i] = fmaf(a[j], bb[i], acc[j][i]);
        }
        __syncthreads();
    }

    // Epilogue: + b2, coalesced float4 stores. Output is (B, T, U, V) row-major
    // = rows (b*TU + r) of a [51200, 1024] matrix.
    float4 c0 = *(const float4*)&b2[n0 + tx * 8];
    float4 c1 = *(const float4*)&b2[n0 + tx * 8 + 4];
    #pragma unroll
    for (int j = 0; j < 4; j++) {
        const size_t row = (size_t)b * TU + m0 + ty * 4 + j;
        float4 o0, o1;
        o0.x = acc[j][0] + c0.x; o0.y = acc[j][1] + c0.y;
        o0.z = acc[j][2] + c0.z; o0.w = acc[j][3] + c0.w;
        o1.x = acc[j][4] + c1.x; o1.y = acc[j][5] + c1.y;
        o1.z = acc[j][6] + c1.z; o1.w = acc[j][7] + c1.w;
        *(float4*)&out[row * VV + n0 + tx * 8]     = o0;
        *(float4*)&out[row * VV + n0 + tx * 8 + 4] = o1;
    }
}

// ---------------------------------------------------------------------------
// Launch
// ---------------------------------------------------------------------------
extern "C" void kernel_launch(void* const* d_in, const int* in_sizes, int n_in,
                              void* d_out, int out_size)
{
    const float* enc = (const float*)d_in[0];   // (4,160,640)
    const float* dec = (const float*)d_in[1];   // (4,80,640)
    const float* W1  = (const float*)d_in[2];   // (1280,640)
    const float* b1  = (const float*)d_in[3];   // (640,)
    const float* W2  = (const float*)d_in[4];   // (640,1024)
    const float* b2  = (const float*)d_in[5];   // (1024,)
    float* out = (float*)d_out;                 // (4,160,80,1024)

    float *pe = nullptr, *pd = nullptr;
    cudaGetSymbolAddress((void**)&pe, g_proj_e);
    cudaGetSymbolAddress((void**)&pd, g_proj_d);

    // enc projection: M = B*T = 640, no bias
    proj_kernel<<<dim3(HH / 64, (B_ * T_) / 64), 256>>>(enc, W1, nullptr, pe);
    // dec projection: M = B*U = 320, fold b1 here
    proj_kernel<<<dim3(HH / 64, (B_ * U_) / 64), 256>>>(dec, W1 + (size_t)DE * HH, b1, pd);
    // fused tanh + GEMM + b2
    joint_kernel<<<dim3(VV / 128, TU / 64, B_), 256>>>(W2, b2, out);
}

// round 3
// speedup vs baseline: 4.3892x; 4.3892x over previous
#include <cuda_runtime.h>
#include <cuda_fp16.h>
#include <cstdint>

// ---------------------------------------------------------------------------
// Problem constants
// ---------------------------------------------------------------------------
#define B_ 4
#define T_ 160
#define U_ 80
#define DE 640
#define HH 640
#define VV 1024
#define TU (T_ * U_)          // 12800
#define MTOT (B_ * TU)        // 51200

// Joint GEMM tiling
#define BM 256
#define BN 128
#define BK 32
#define KITERS (HH / BK)      // 20

// ---------------------------------------------------------------------------
// Device scratch (allocation-free rule)
// ---------------------------------------------------------------------------
__device__ float g_proj_e[B_ * T_ * HH];
__device__ float g_proj_d[B_ * U_ * HH];
__device__ __align__(16) __half g_A[(size_t)MTOT * HH];   // fp16(tanh(...))
__device__ __align__(16) __half g_Bhi[VV * HH];           // W2^T hi, [n][k]
__device__ __align__(16) __half g_Blo[VV * HH];           // W2^T lo, [n][k]

// ---------------------------------------------------------------------------
// Helpers
// ---------------------------------------------------------------------------
__device__ __forceinline__ uint32_t smem_u32(const void* p) {
    uint32_t a;
    asm("{ .reg .u64 t; cvta.to.shared.u64 t, %1; cvt.u32.u64 %0, t; }"
        : "=r"(a) : "l"(p));
    return a;
}

__device__ __forceinline__ float fast_tanh(float x) {
    float e;
    asm("ex2.approx.f32 %0, %1;" : "=f"(e) : "f"(x * 2.885390081777927f));
    float r;
    asm("rcp.approx.f32 %0, %1;" : "=f"(r) : "f"(e + 1.0f));
    return fmaf(-2.0f, r, 1.0f);
}

#define CP_ASYNC16(saddr, gptr) \
    asm volatile("cp.async.cg.shared.global [%0], [%1], 16;" \
                 :: "r"(saddr), "l"(gptr))
#define CP_COMMIT()  asm volatile("cp.async.commit_group;" ::: "memory")
#define CP_WAIT1()   asm volatile("cp.async.wait_group 1;" ::: "memory")
#define CP_WAIT0()   asm volatile("cp.async.wait_group 0;" ::: "memory")

#define LDSM4(r0, r1, r2, r3, a) \
    asm volatile("ldmatrix.sync.aligned.m8n8.x4.shared.b16 {%0,%1,%2,%3}, [%4];" \
                 : "=r"(r0), "=r"(r1), "=r"(r2), "=r"(r3) : "r"(a))

#define MMA16816(d, a, b0, b1) \
    asm volatile("mma.sync.aligned.m16n8k16.row.col.f32.f16.f16.f32 " \
                 "{%0,%1,%2,%3}, {%4,%5,%6,%7}, {%8,%9}, {%0,%1,%2,%3};" \
                 : "+f"((d)[0]), "+f"((d)[1]), "+f"((d)[2]), "+f"((d)[3]) \
                 : "r"((a)[0]), "r"((a)[1]), "r"((a)[2]), "r"((a)[3]), \
                   "r"(b0), "r"(b1))

// ---------------------------------------------------------------------------
// Stage 1: projections (SIMT; small)
// ---------------------------------------------------------------------------
__global__ void proj_kernel(const float* __restrict__ A,
                            const float* __restrict__ W,
                            const float* __restrict__ bias,
                            float* __restrict__ C)
{
    __shared__ float As[16][65];
    __shared__ float Bs[16][64];

    const int ltid = threadIdx.x;
    const int m0 = blockIdx.y * 64;
    const int n0 = blockIdx.x * 64;

    const int arow = ltid >> 2;
    const int ak4  = (ltid & 3) * 4;
    const int bk   = ltid >> 4;
    const int bn   = (ltid & 15) * 4;
    const int tx = ltid & 15;
    const int ty = ltid >> 4;

    float acc[4][4] = {};

    for (int k0 = 0; k0 < DE; k0 += 16) {
        float4 av = *(const float4*)&A[(size_t)(m0 + arow) * DE + k0 + ak4];
        As[ak4 + 0][arow] = av.x;
        As[ak4 + 1][arow] = av.y;
        As[ak4 + 2][arow] = av.z;
        As[ak4 + 3][arow] = av.w;
        *(float4*)&Bs[bk][bn] = *(const float4*)&W[(size_t)(k0 + bk) * HH + n0 + bn];
        __syncthreads();
        #pragma unroll
        for (int k = 0; k < 16; k++) {
            float a[4], b[4];
            #pragma unroll
            for (int j = 0; j < 4; j++) a[j] = As[k][ty * 4 + j];
            #pragma unroll
            for (int i = 0; i < 4; i++) b[i] = Bs[k][tx * 4 + i];
            #pragma unroll
            for (int j = 0; j < 4; j++)
                #pragma unroll
                for (int i = 0; i < 4; i++)
                    acc[j][i] = fmaf(a[j], b[i], acc[j][i]);
        }
        __syncthreads();
    }

    #pragma unroll
    for (int j = 0; j < 4; j++) {
        const int row = m0 + ty * 4 + j;
        #pragma unroll
        for (int i = 0; i < 4; i++) {
            float v = acc[j][i];
            if (bias) v += bias[n0 + tx * 4 + i];
            C[(size_t)row * HH + n0 + tx * 4 + i] = v;
        }
    }
}

// ---------------------------------------------------------------------------
// Stage 1.5a: W2 transpose + fp16 hi/lo split (W2T[n][k] = W2[k][n])
// ---------------------------------------------------------------------------
__global__ void prep_w2(const float* __restrict__ W2,
                        __half* __restrict__ hi,
                        __half* __restrict__ lo)
{
    int idx = blockIdx.x * 256 + threadIdx.x;   // n*HH + k (exact grid)
    int n = idx / HH;
    int k = idx - n * HH;
    float w = W2[(size_t)k * VV + n];
    __half h = __float2half_rn(w);
    __half l = __float2half_rn(w - __half2float(h));
    hi[idx] = h;
    lo[idx] = l;
}

// ---------------------------------------------------------------------------
// Stage 1.5b: A = fp16(tanh(pe + pd)), materialized [MTOT][HH]
// ---------------------------------------------------------------------------
__global__ void prep_a(__half* __restrict__ A)
{
    int idx = blockIdx.x * 256 + threadIdx.x;   // over MTOT*160 float4s (exact)
    int row = idx / 160;
    int q = idx - row * 160;
    int b = row / TU;
    int rem = row - b * TU;
    int t = rem / U_;
    int u = rem - t * U_;

    const float4 e = *(const float4*)&g_proj_e[(size_t)(b * T_ + t) * HH + q * 4];
    const float4 d = *(const float4*)&g_proj_d[(size_t)(b * U_ + u) * HH + q * 4];

    __half h[4];
    h[0] = __float2half_rn(fast_tanh(e.x + d.x));
    h[1] = __float2half_rn(fast_tanh(e.y + d.y));
    h[2] = __float2half_rn(fast_tanh(e.z + d.z));
    h[3] = __float2half_rn(fast_tanh(e.w + d.w));
    *(uint2*)&A[(size_t)row * HH + q * 4] = *(uint2*)h;
}

// ---------------------------------------------------------------------------
// Stage 2: HMMA joint GEMM.  out[51200,1024] = A@Bhi^T + A@Blo^T + b2
// BM=256, BN=128, BK=32; 512 threads = 16 warps (4M x 4N), warp tile 64x32.
// Double-buffered cp.async; xor-swizzled smem for conflict-free ldmatrix.
// smem per buffer: A 16KB @0, Bhi 8KB @16K, Blo 8KB @24K; buffers @0, @32K.
// ---------------------------------------------------------------------------
#define SMEM_TOTAL 65536

__device__ __forceinline__ void load_buf(uint32_t sbuf,
                                         const __half* __restrict__ A,
                                         const __half* __restrict__ Bhi,
                                         const __half* __restrict__ Blo,
                                         int m0, int n0, int k0)
{
    const int tid = threadIdx.x;
    // A tile: 256 rows x 32 halfs = 1024 16B-chunks (4/row)
    #pragma unroll
    for (int i = 0; i < 2; i++) {
        int ci = tid + i * 512;
        int row = ci >> 2;
        int ck = ci & 3;
        uint32_t so = sbuf + row * 64 + ((ck ^ ((row >> 1) & 3)) << 4);
        const __half* gp = A + (size_t)(m0 + row) * HH + k0 + ck * 8;
        CP_ASYNC16(so, gp);
    }
    // Bhi / Blo tiles: 128 rows x 32 halfs = 512 chunks each
    {
        int row = tid >> 2, ck = tid & 3;
        uint32_t sw = row * 64 + ((ck ^ ((row >> 1) & 3)) << 4);
        const __half* gh = Bhi + (size_t)(n0 + row) * HH + k0 + ck * 8;
        const __half* gl = Blo + (size_t)(n0 + row) * HH + k0 + ck * 8;
        CP_ASYNC16(sbuf + 16384u + sw, gh);
        CP_ASYNC16(sbuf + 24576u + sw, gl);
    }
}

__global__ void __launch_bounds__(512, 1)
joint_gemm(const __half* __restrict__ A,
           const __half* __restrict__ Bhi,
           const __half* __restrict__ Blo,
           const float* __restrict__ b2,
           float* __restrict__ out)
{
    extern __shared__ __align__(1024) char smem[];
    const uint32_t sb = smem_u32(smem);

    const int tid  = threadIdx.x;
    const int lane = tid & 31;
    const int wid  = tid >> 5;
    const int wm   = wid & 3;          // 0..3 -> 64-row stripes
    const int wn   = wid >> 2;         // 0..3 -> 32-col stripes
    const int n0   = blockIdx.x * BN;
    const int m0   = blockIdx.y * BM;

    const int lml = lane & 15;
    const int lmh = lane >> 4;
    const uint32_t xorv = (lml >> 1) & 3;

    float acc[4][4][4];
    #pragma unroll
    for (int a = 0; a < 4; a++)
        #pragma unroll
        for (int n = 0; n < 4; n++)
            #pragma unroll
            for (int i = 0; i < 4; i++) acc[a][n][i] = 0.0f;

    // prologue: fill both buffers
    load_buf(sb,          A, Bhi, Blo, m0, n0, 0);
    CP_COMMIT();
    load_buf(sb + 32768u, A, Bhi, Blo, m0, n0, BK);
    CP_COMMIT();
    CP_WAIT1();
    __syncthreads();

    for (int c = 0; c < KITERS; c++) {
        const uint32_t sbuf = sb + (uint32_t)(c & 1) * 32768u;

        #pragma unroll
        for (int ks = 0; ks < 2; ks++) {
            const uint32_t ckk = (uint32_t)((2 * ks + lmh) ^ xorv) << 4;

            // A fragments (4 m-atoms)
            uint32_t af[4][4];
            #pragma unroll
            for (int a = 0; a < 4; a++) {
                uint32_t row = (uint32_t)(wm * 64 + a * 16 + lml);
                LDSM4(af[a][0], af[a][1], af[a][2], af[a][3],
                      sbuf + row * 64 + ckk);
            }
            // B hi fragments (4 n-atoms via 2 x ldmatrix.x4)
            uint32_t bf[2][4];
            #pragma unroll
            for (int p = 0; p < 2; p++) {
                uint32_t row = (uint32_t)(wn * 32 + p * 16 + lml);
                LDSM4(bf[p][0], bf[p][1], bf[p][2], bf[p][3],
                      sbuf + 16384u + row * 64 + ckk);
            }
            #pragma unroll
            for (int a = 0; a < 4; a++)
                #pragma unroll
                for (int n = 0; n < 4; n++) {
                    int p = n >> 1, s = n & 1;
                    MMA16816(acc[a][n], af[a], bf[p][s], bf[p][s + 2]);
                }
            // B lo fragments (reuse regs)
            #pragma unroll
            for (int p = 0; p < 2; p++) {
                uint32_t row = (uint32_t)(wn * 32 + p * 16 + lml);
                LDSM4(bf[p][0], bf[p][1], bf[p][2], bf[p][3],
                      sbuf + 24576u + row * 64 + ckk);
            }
            #pragma unroll
            for (int a = 0; a < 4; a++)
                #pragma unroll
                for (int n = 0; n < 4; n++) {
                    int p = n >> 1, s = n & 1;
                    MMA16816(acc[a][n], af[a], bf[p][s], bf[p][s + 2]);
                }
        }

        __syncthreads();   // everyone done reading this buffer
        if (c + 2 < KITERS) {
            load_buf(sb + (uint32_t)(c & 1) * 32768u, A, Bhi, Blo,
                     m0, n0, (c + 2) * BK);
            CP_COMMIT();
            CP_WAIT1();
        } else {
            CP_WAIT0();
        }
        __syncthreads();   // next buffer visible to all
    }

    // epilogue: +b2, direct stores
    #pragma unroll
    for (int n = 0; n < 4; n++) {
        const int col = n0 + wn * 32 + n * 8 + (lane & 3) * 2;
        const float2 bb = *(const float2*)&b2[col];
        #pragma unroll
        for (int a = 0; a < 4; a++) {
            const size_t r0 = (size_t)m0 + wm * 64 + a * 16 + (lane >> 2);
            float2 o0 = { acc[a][n][0] + bb.x, acc[a][n][1] + bb.y };
            float2 o1 = { acc[a][n][2] + bb.x, acc[a][n][3] + bb.y };
            *(float2*)&out[r0 * VV + col]       = o0;
            *(float2*)&out[(r0 + 8) * VV + col] = o1;
        }
    }
}

// ---------------------------------------------------------------------------
// Launch
// ---------------------------------------------------------------------------
extern "C" void kernel_launch(void* const* d_in, const int* in_sizes, int n_in,
                              void* d_out, int out_size)
{
    const float* enc = (const float*)d_in[0];
    const float* dec = (const float*)d_in[1];
    const float* W1  = (const float*)d_in[2];
    const float* b1  = (const float*)d_in[3];
    const float* W2  = (const float*)d_in[4];
    const float* b2  = (const float*)d_in[5];
    float* out = (float*)d_out;

    float *pe = nullptr, *pd = nullptr;
    __half *ga = nullptr, *gbh = nullptr, *gbl = nullptr;
    cudaGetSymbolAddress((void**)&pe,  g_proj_e);
    cudaGetSymbolAddress((void**)&pd,  g_proj_d);
    cudaGetSymbolAddress((void**)&ga,  g_A);
    cudaGetSymbolAddress((void**)&gbh, g_Bhi);
    cudaGetSymbolAddress((void**)&gbl, g_Blo);

    cudaFuncSetAttribute(joint_gemm,
                         cudaFuncAttributeMaxDynamicSharedMemorySize, SMEM_TOTAL);

    proj_kernel<<<dim3(HH / 64, (B_ * T_) / 64), 256>>>(enc, W1, nullptr, pe);
    proj_kernel<<<dim3(HH / 64, (B_ * U_) / 64), 256>>>(dec, W1 + (size_t)DE * HH, b1, pd);

    prep_w2<<<(VV * HH) / 256, 256>>>(W2, gbh, gbl);
    prep_a<<<(MTOT * 160) / 256, 256>>>(ga);

    // grid.x = n-blocks (fastest) so CTAs sharing an A stripe co-run -> L2 reuse
    joint_gemm<<<dim3(VV / BN, MTOT / BM), 512, SMEM_TOTAL>>>(ga, gbh, gbl, b2, out);
}

// round 4
// speedup vs baseline: 7.8074x; 1.7788x over previous
#include <cuda_runtime.h>
#include <cuda_fp16.h>
#include <cstdint>

// ---------------------------------------------------------------------------
// Problem constants
// ---------------------------------------------------------------------------
#define B_ 4
#define T_ 160
#define U_ 80
#define DE 640
#define HH 640
#define VV 1024
#define TU (T_ * U_)          // 12800
#define MTOT (B_ * TU)        // 51200

// Joint GEMM tiling
#define BM 256
#define BN 128
#define BK 64
#define KITERS (HH / BK)      // 10

// ---------------------------------------------------------------------------
// Device scratch (allocation-free rule)
// ---------------------------------------------------------------------------
__device__ float g_proj_e[B_ * T_ * HH];
__device__ float g_proj_d[B_ * U_ * HH];
__device__ __align__(16) __half g_A[(size_t)MTOT * HH];   // fp16(tanh(...))
__device__ __align__(16) __half g_B[VV * HH];             // W2^T fp16, [n][k]

// ---------------------------------------------------------------------------
// Helpers
// ---------------------------------------------------------------------------
__device__ __forceinline__ uint32_t smem_u32(const void* p) {
    uint32_t a;
    asm("{ .reg .u64 t; cvta.to.shared.u64 t, %1; cvt.u32.u64 %0, t; }"
        : "=r"(a) : "l"(p));
    return a;
}

__device__ __forceinline__ float fast_tanh(float x) {
    float e;
    asm("ex2.approx.f32 %0, %1;" : "=f"(e) : "f"(x * 2.885390081777927f));
    float r;
    asm("rcp.approx.f32 %0, %1;" : "=f"(r) : "f"(e + 1.0f));
    return fmaf(-2.0f, r, 1.0f);
}

#define CP_ASYNC16(saddr, gptr) \
    asm volatile("cp.async.cg.shared.global [%0], [%1], 16;" \
                 :: "r"(saddr), "l"(gptr))
#define CP_COMMIT()  asm volatile("cp.async.commit_group;" ::: "memory")
#define CP_WAIT1()   asm volatile("cp.async.wait_group 1;" ::: "memory")
#define CP_WAIT0()   asm volatile("cp.async.wait_group 0;" ::: "memory")

#define LDSM4(r0, r1, r2, r3, a) \
    asm volatile("ldmatrix.sync.aligned.m8n8.x4.shared.b16 {%0,%1,%2,%3}, [%4];" \
                 : "=r"(r0), "=r"(r1), "=r"(r2), "=r"(r3) : "r"(a))

#define MMA16816(d, a, b0, b1) \
    asm volatile("mma.sync.aligned.m16n8k16.row.col.f32.f16.f16.f32 " \
                 "{%0,%1,%2,%3}, {%4,%5,%6,%7}, {%8,%9}, {%0,%1,%2,%3};" \
                 : "+f"((d)[0]), "+f"((d)[1]), "+f"((d)[2]), "+f"((d)[3]) \
                 : "r"((a)[0]), "r"((a)[1]), "r"((a)[2]), "r"((a)[3]), \
                   "r"(b0), "r"(b1))

// ---------------------------------------------------------------------------
// Stage 1: both projections in ONE launch (grid.y 0..9 = enc, 10..14 = dec)
// ---------------------------------------------------------------------------
__global__ void proj_both(const float* __restrict__ enc,
                          const float* __restrict__ dec,
                          const float* __restrict__ W1,
                          const float* __restrict__ b1,
                          float* __restrict__ pe,
                          float* __restrict__ pd)
{
    __shared__ float As[16][65];
    __shared__ float Bs[16][64];

    const int ltid = threadIdx.x;
    const bool is_dec = (blockIdx.y >= 10);
    const int m0 = (is_dec ? (blockIdx.y - 10) : blockIdx.y) * 64;
    const int n0 = blockIdx.x * 64;

    const float* __restrict__ A    = is_dec ? dec : enc;
    const float* __restrict__ W    = is_dec ? (W1 + (size_t)DE * HH) : W1;
    const float* __restrict__ bias = is_dec ? b1 : nullptr;
    float* __restrict__ C          = is_dec ? pd : pe;

    const int arow = ltid >> 2;
    const int ak4  = (ltid & 3) * 4;
    const int bk   = ltid >> 4;
    const int bn   = (ltid & 15) * 4;
    const int tx = ltid & 15;
    const int ty = ltid >> 4;

    float acc[4][4] = {};

    for (int k0 = 0; k0 < DE; k0 += 16) {
        float4 av = *(const float4*)&A[(size_t)(m0 + arow) * DE + k0 + ak4];
        As[ak4 + 0][arow] = av.x;
        As[ak4 + 1][arow] = av.y;
        As[ak4 + 2][arow] = av.z;
        As[ak4 + 3][arow] = av.w;
        *(float4*)&Bs[bk][bn] = *(const float4*)&W[(size_t)(k0 + bk) * HH + n0 + bn];
        __syncthreads();
        #pragma unroll
        for (int k = 0; k < 16; k++) {
            float a[4], b[4];
            #pragma unroll
            for (int j = 0; j < 4; j++) a[j] = As[k][ty * 4 + j];
            #pragma unroll
            for (int i = 0; i < 4; i++) b[i] = Bs[k][tx * 4 + i];
            #pragma unroll
            for (int j = 0; j < 4; j++)
                #pragma unroll
                for (int i = 0; i < 4; i++)
                    acc[j][i] = fmaf(a[j], b[i], acc[j][i]);
        }
        __syncthreads();
    }

    #pragma unroll
    for (int j = 0; j < 4; j++) {
        const int row = m0 + ty * 4 + j;
        #pragma unroll
        for (int i = 0; i < 4; i++) {
            float v = acc[j][i];
            if (bias) v += bias[n0 + tx * 4 + i];
            C[(size_t)row * HH + n0 + tx * 4 + i] = v;
        }
    }
}

// ---------------------------------------------------------------------------
// Stage 1.5a: W2 transpose + fp16 (B[n][k] = fp16(W2[k][n]))
// ---------------------------------------------------------------------------
__global__ void prep_w2(const float* __restrict__ W2, __half* __restrict__ B)
{
    int idx = blockIdx.x * 256 + threadIdx.x;   // n*HH + k (exact grid)
    int n = idx / HH;
    int k = idx - n * HH;
    B[idx] = __float2half_rn(W2[(size_t)k * VV + n]);
}

// ---------------------------------------------------------------------------
// Stage 1.5b: A = fp16(tanh(pe + pd)), materialized [MTOT][HH]
// ---------------------------------------------------------------------------
__global__ void prep_a(__half* __restrict__ A)
{
    int idx = blockIdx.x * 256 + threadIdx.x;   // over MTOT*160 float4s (exact)
    int row = idx / 160;
    int q = idx - row * 160;
    int b = row / TU;
    int rem = row - b * TU;
    int t = rem / U_;
    int u = rem - t * U_;

    const float4 e = *(const float4*)&g_proj_e[(size_t)(b * T_ + t) * HH + q * 4];
    const float4 d = *(const float4*)&g_proj_d[(size_t)(b * U_ + u) * HH + q * 4];

    __half h[4];
    h[0] = __float2half_rn(fast_tanh(e.x + d.x));
    h[1] = __float2half_rn(fast_tanh(e.y + d.y));
    h[2] = __float2half_rn(fast_tanh(e.z + d.z));
    h[3] = __float2half_rn(fast_tanh(e.w + d.w));
    *(uint2*)&A[(size_t)row * HH + q * 4] = *(uint2*)h;
}

// ---------------------------------------------------------------------------
// Stage 2: HMMA joint GEMM (single pass fp16).
// out[51200,1024] = A@B^T + b2.  BM=256, BN=128, BK=64; 512 thr = 16 warps.
// smem: per buffer A 32KB @0, B 16KB @32K; buffer stride 48KB; total 96KB.
// Row = 128 bytes (8 x 16B chunks); swizzle: chunk ^= (row & 7).
// ---------------------------------------------------------------------------
#define BUF_STRIDE 49152u
#define SMEM_TOTAL (2 * 49152)

__device__ __forceinline__ void load_buf(uint32_t sbuf,
                                         const __half* __restrict__ A,
                                         const __half* __restrict__ B,
                                         int m0, int n0, int k0)
{
    const int tid = threadIdx.x;
    // A tile: 256 rows x 64 halfs = 2048 16B-chunks (8/row), 4 per thread
    #pragma unroll
    for (int i = 0; i < 4; i++) {
        int ci = tid + i * 512;
        int row = ci >> 3;
        int ck = ci & 7;
        uint32_t so = sbuf + row * 128 + ((ck ^ (row & 7)) << 4);
        CP_ASYNC16(so, A + (size_t)(m0 + row) * HH + k0 + ck * 8);
    }
    // B tile: 128 rows x 64 halfs = 1024 chunks, 2 per thread
    #pragma unroll
    for (int i = 0; i < 2; i++) {
        int ci = tid + i * 512;
        int row = ci >> 3;
        int ck = ci & 7;
        uint32_t so = sbuf + 32768u + row * 128 + ((ck ^ (row & 7)) << 4);
        CP_ASYNC16(so, B + (size_t)(n0 + row) * HH + k0 + ck * 8);
    }
}

__global__ void __launch_bounds__(512, 1)
joint_gemm(const __half* __restrict__ A,
           const __half* __restrict__ B,
           const float* __restrict__ b2,
           float* __restrict__ out)
{
    extern __shared__ __align__(1024) char smem[];
    const uint32_t sb = smem_u32(smem);

    const int tid  = threadIdx.x;
    const int lane = tid & 31;
    const int wid  = tid >> 5;
    const int wm   = wid & 3;          // 0..3 -> 64-row stripes
    const int wn   = wid >> 2;         // 0..3 -> 32-col stripes
    const int n0   = blockIdx.x * BN;
    const int m0   = blockIdx.y * BM;

    const int lml = lane & 15;         // ldmatrix row within 16
    const int lmh = lane >> 4;         // ldmatrix 16B-chunk select

    float acc[4][4][4];
    #pragma unroll
    for (int a = 0; a < 4; a++)
        #pragma unroll
        for (int n = 0; n < 4; n++)
            #pragma unroll
            for (int i = 0; i < 4; i++) acc[a][n][i] = 0.0f;

    load_buf(sb,              A, B, m0, n0, 0);
    CP_COMMIT();
    load_buf(sb + BUF_STRIDE, A, B, m0, n0, BK);
    CP_COMMIT();
    CP_WAIT1();
    __syncthreads();

    for (int c = 0; c < KITERS; c++) {
        const uint32_t sbuf = sb + (uint32_t)(c & 1) * BUF_STRIDE;

        #pragma unroll
        for (int ks = 0; ks < 4; ks++) {
            const int ck = 2 * ks + lmh;

            uint32_t af[4][4];
            #pragma unroll
            for (int a = 0; a < 4; a++) {
                uint32_t row = (uint32_t)(wm * 64 + a * 16 + lml);
                LDSM4(af[a][0], af[a][1], af[a][2], af[a][3],
                      sbuf + row * 128 + (uint32_t)((ck ^ (row & 7)) << 4));
            }
            uint32_t bf[2][4];
            #pragma unroll
            for (int p = 0; p < 2; p++) {
                uint32_t row = (uint32_t)(wn * 32 + p * 16 + lml);
                LDSM4(bf[p][0], bf[p][1], bf[p][2], bf[p][3],
                      sbuf + 32768u + row * 128 +
                      (uint32_t)((ck ^ (row & 7)) << 4));
            }
            #pragma unroll
            for (int a = 0; a < 4; a++)
                #pragma unroll
                for (int n = 0; n < 4; n++) {
                    int p = n >> 1, s = n & 1;
                    MMA16816(acc[a][n], af[a], bf[p][s], bf[p][s + 2]);
                }
        }

        __syncthreads();   // all warps done reading this buffer
        if (c + 2 < KITERS) {
            load_buf(sb + (uint32_t)(c & 1) * BUF_STRIDE, A, B,
                     m0, n0, (c + 2) * BK);
            CP_COMMIT();
            CP_WAIT1();
        } else {
            CP_WAIT0();
        }
        __syncthreads();   // next buffer visible
    }

    // epilogue: +b2, direct stores
    #pragma unroll
    for (int n = 0; n < 4; n++) {
        const int col = n0 + wn * 32 + n * 8 + (lane & 3) * 2;
        const float2 bb = *(const float2*)&b2[col];
        #pragma unroll
        for (int a = 0; a < 4; a++) {
            const size_t r0 = (size_t)m0 + wm * 64 + a * 16 + (lane >> 2);
            float2 o0 = { acc[a][n][0] + bb.x, acc[a][n][1] + bb.y };
            float2 o1 = { acc[a][n][2] + bb.x, acc[a][n][3] + bb.y };
            *(float2*)&out[r0 * VV + col]       = o0;
            *(float2*)&out[(r0 + 8) * VV + col] = o1;
        }
    }
}

// ---------------------------------------------------------------------------
// Launch
// ---------------------------------------------------------------------------
extern "C" void kernel_launch(void* const* d_in, const int* in_sizes, int n_in,
                              void* d_out, int out_size)
{
    const float* enc = (const float*)d_in[0];
    const float* dec = (const float*)d_in[1];
    const float* W1  = (const float*)d_in[2];
    const float* b1  = (const float*)d_in[3];
    const float* W2  = (const float*)d_in[4];
    const float* b2  = (const float*)d_in[5];
    float* out = (float*)d_out;

    float *pe = nullptr, *pd = nullptr;
    __half *ga = nullptr, *gb = nullptr;
    cudaGetSymbolAddress((void**)&pe, g_proj_e);
    cudaGetSymbolAddress((void**)&pd, g_proj_d);
    cudaGetSymbolAddress((void**)&ga, g_A);
    cudaGetSymbolAddress((void**)&gb, g_B);

    cudaFuncSetAttribute(joint_gemm,
                         cudaFuncAttributeMaxDynamicSharedMemorySize, SMEM_TOTAL);

    // both projections in one launch (y 0..9 enc, 10..14 dec)
    proj_both<<<dim3(HH / 64, 15), 256>>>(enc, dec, W1, b1, pe, pd);

    prep_w2<<<(VV * HH) / 256, 256>>>(W2, gb);
    prep_a<<<(MTOT * 160) / 256, 256>>>(ga);

    // grid.x = n-blocks (fastest) so CTAs sharing an A stripe co-run
    joint_gemm<<<dim3(VV / BN, MTOT / BM), 512, SMEM_TOTAL>>>(ga, gb, b2, out);
}

// round 5
// speedup vs baseline: 8.1869x; 1.0486x over previous
#include <cuda_runtime.h>
#include <cuda_fp16.h>
#include <cstdint>

// ---------------------------------------------------------------------------
// Problem constants
// ---------------------------------------------------------------------------
#define B_ 4
#define T_ 160
#define U_ 80
#define DE 640
#define HH 640
#define VV 1024
#define TU (T_ * U_)          // 12800
#define MTOT (B_ * TU)        // 51200

// Joint GEMM tiling
#define BM 128
#define BN 128
#define BK 64
#define KITERS (HH / BK)      // 10
#define STAGES 3

// ---------------------------------------------------------------------------
// Device scratch
// ---------------------------------------------------------------------------
__device__ float g_proj_e[B_ * T_ * HH];
__device__ float g_proj_d[B_ * U_ * HH];
__device__ __align__(16) __half g_A[(size_t)MTOT * HH];   // fp16(tanh(...))
__device__ __align__(16) __half g_B[VV * HH];             // W2^T fp16, [n][k]

// ---------------------------------------------------------------------------
// Helpers
// ---------------------------------------------------------------------------
__device__ __forceinline__ uint32_t smem_u32(const void* p) {
    uint32_t a;
    asm("{ .reg .u64 t; cvta.to.shared.u64 t, %1; cvt.u32.u64 %0, t; }"
        : "=r"(a) : "l"(p));
    return a;
}

__device__ __forceinline__ float fast_tanh(float x) {
    float e;
    asm("ex2.approx.f32 %0, %1;" : "=f"(e) : "f"(x * 2.885390081777927f));
    float r;
    asm("rcp.approx.f32 %0, %1;" : "=f"(r) : "f"(e + 1.0f));
    return fmaf(-2.0f, r, 1.0f);
}

#define CP_ASYNC16(saddr, gptr) \
    asm volatile("cp.async.cg.shared.global [%0], [%1], 16;" \
                 :: "r"(saddr), "l"(gptr))
#define CP_COMMIT()  asm volatile("cp.async.commit_group;" ::: "memory")
#define CP_WAIT1()   asm volatile("cp.async.wait_group 1;" ::: "memory")
#define CP_WAIT0()   asm volatile("cp.async.wait_group 0;" ::: "memory")

#define LDSM4(r0, r1, r2, r3, a) \
    asm volatile("ldmatrix.sync.aligned.m8n8.x4.shared.b16 {%0,%1,%2,%3}, [%4];" \
                 : "=r"(r0), "=r"(r1), "=r"(r2), "=r"(r3) : "r"(a))

#define MMA16816(d, a, b0, b1) \
    asm volatile("mma.sync.aligned.m16n8k16.row.col.f32.f16.f16.f32 " \
                 "{%0,%1,%2,%3}, {%4,%5,%6,%7}, {%8,%9}, {%0,%1,%2,%3};" \
                 : "+f"((d)[0]), "+f"((d)[1]), "+f"((d)[2]), "+f"((d)[3]) \
                 : "r"((a)[0]), "r"((a)[1]), "r"((a)[2]), "r"((a)[3]), \
                   "r"(b0), "r"(b1))

// ---------------------------------------------------------------------------
// Stage 1: both projections, one launch, register-prefetch double buffering
// grid.y 0..9 = enc (m 0..639), 10..14 = dec (m 0..319)
// ---------------------------------------------------------------------------
__global__ void proj_both(const float* __restrict__ enc,
                          const float* __restrict__ dec,
                          const float* __restrict__ W1,
                          const float* __restrict__ b1,
                          float* __restrict__ pe,
                          float* __restrict__ pd)
{
    __shared__ float As[16][65];
    __shared__ float Bs[16][64];

    const int ltid = threadIdx.x;
    const bool is_dec = (blockIdx.y >= 10);
    const int m0 = (is_dec ? (blockIdx.y - 10) : blockIdx.y) * 64;
    const int n0 = blockIdx.x * 64;

    const float* __restrict__ A    = is_dec ? dec : enc;
    const float* __restrict__ W    = is_dec ? (W1 + (size_t)DE * HH) : W1;
    const float* __restrict__ bias = is_dec ? b1 : nullptr;
    float* __restrict__ C          = is_dec ? pd : pe;

    const int arow = ltid >> 2;
    const int ak4  = (ltid & 3) * 4;
    const int bk   = ltid >> 4;
    const int bn   = (ltid & 15) * 4;
    const int tx = ltid & 15;
    const int ty = ltid >> 4;

    float acc[4][4] = {};

    // prefetch k0 = 0
    float4 av = *(const float4*)&A[(size_t)(m0 + arow) * DE + ak4];
    float4 bv = *(const float4*)&W[(size_t)bk * HH + n0 + bn];

    for (int k0 = 0; k0 < DE; k0 += 16) {
        As[ak4 + 0][arow] = av.x;
        As[ak4 + 1][arow] = av.y;
        As[ak4 + 2][arow] = av.z;
        As[ak4 + 3][arow] = av.w;
        *(float4*)&Bs[bk][bn] = bv;
        __syncthreads();

        if (k0 + 16 < DE) {   // prefetch next tile while computing
            av = *(const float4*)&A[(size_t)(m0 + arow) * DE + k0 + 16 + ak4];
            bv = *(const float4*)&W[(size_t)(k0 + 16 + bk) * HH + n0 + bn];
        }

        #pragma unroll
        for (int k = 0; k < 16; k++) {
            float a[4], b[4];
            #pragma unroll
            for (int j = 0; j < 4; j++) a[j] = As[k][ty * 4 + j];
            #pragma unroll
            for (int i = 0; i < 4; i++) b[i] = Bs[k][tx * 4 + i];
            #pragma unroll
            for (int j = 0; j < 4; j++)
                #pragma unroll
                for (int i = 0; i < 4; i++)
                    acc[j][i] = fmaf(a[j], b[i], acc[j][i]);
        }
        __syncthreads();
    }

    #pragma unroll
    for (int j = 0; j < 4; j++) {
        const int row = m0 + ty * 4 + j;
        #pragma unroll
        for (int i = 0; i < 4; i++) {
            float v = acc[j][i];
            if (bias) v += bias[n0 + tx * 4 + i];
            C[(size_t)row * HH + n0 + tx * 4 + i] = v;
        }
    }
}

// ---------------------------------------------------------------------------
// Stage 1.5a: W2 transpose -> fp16, tiled through smem (coalesced both ways)
// grid: (VV/32, HH/32), 256 threads
// ---------------------------------------------------------------------------
__global__ void prep_w2(const float* __restrict__ W2, __half* __restrict__ B)
{
    __shared__ float tile[32][33];
    const int n0 = blockIdx.x * 32;
    const int k0 = blockIdx.y * 32;
    const int x = threadIdx.x & 31;
    const int y = threadIdx.x >> 5;        // 0..7

    #pragma unroll
    for (int j = 0; j < 4; j++)            // read W2[k0+ky][n0+x] coalesced
        tile[y + j * 8][x] = W2[(size_t)(k0 + y + j * 8) * VV + n0 + x];
    __syncthreads();

    #pragma unroll
    for (int j = 0; j < 4; j++) {          // write B[n0+ny][k0+x] coalesced
        int ny = y + j * 8;
        B[(size_t)(n0 + ny) * HH + k0 + x] = __float2half_rn(tile[x][ny]);
    }
}

// ---------------------------------------------------------------------------
// Stage 1.5b: A = fp16(tanh(pe + pd))
// ---------------------------------------------------------------------------
__global__ void prep_a(__half* __restrict__ A)
{
    int idx = blockIdx.x * 256 + threadIdx.x;   // MTOT*160 float4s (exact)
    int row = idx / 160;
    int q = idx - row * 160;
    int b = row / TU;
    int rem = row - b * TU;
    int t = rem / U_;
    int u = rem - t * U_;

    const float4 e = *(const float4*)&g_proj_e[(size_t)(b * T_ + t) * HH + q * 4];
    const float4 d = *(const float4*)&g_proj_d[(size_t)(b * U_ + u) * HH + q * 4];

    __half h[4];
    h[0] = __float2half_rn(fast_tanh(e.x + d.x));
    h[1] = __float2half_rn(fast_tanh(e.y + d.y));
    h[2] = __float2half_rn(fast_tanh(e.z + d.z));
    h[3] = __float2half_rn(fast_tanh(e.w + d.w));
    *(uint2*)&A[(size_t)row * HH + q * 4] = *(uint2*)h;
}

// ---------------------------------------------------------------------------
// Stage 2: HMMA joint GEMM. out[51200,1024] = A@B^T + b2.
// BM=128, BN=128, BK=64; 256 thr = 8 warps (2M x 4N), warp tile 64x32.
// 3-stage cp.async pipeline, ONE __syncthreads per k-iter, 2 CTAs/SM.
// smem/stage: A 16KB @0, B 16KB @16K; stage stride 32KB; total 96KB.
// ---------------------------------------------------------------------------
#define STG_STRIDE 32768u
#define SMEM_TOTAL (STAGES * 32768)

__device__ __forceinline__ void load_buf(uint32_t sbuf,
                                         const __half* __restrict__ A,
                                         const __half* __restrict__ B,
                                         int m0, int n0, int k0)
{
    const int tid = threadIdx.x;
    // A tile: 128 rows x 64 halfs = 1024 16B-chunks, 4 per thread
    #pragma unroll
    for (int i = 0; i < 4; i++) {
        int ci = tid + i * 256;
        int row = ci >> 3;
        int ck = ci & 7;
        uint32_t so = sbuf + row * 128 + ((ck ^ (row & 7)) << 4);
        CP_ASYNC16(so, A + (size_t)(m0 + row) * HH + k0 + ck * 8);
    }
    // B tile: 128 rows x 64 halfs = 1024 chunks, 4 per thread
    #pragma unroll
    for (int i = 0; i < 4; i++) {
        int ci = tid + i * 256;
        int row = ci >> 3;
        int ck = ci & 7;
        uint32_t so = sbuf + 16384u + row * 128 + ((ck ^ (row & 7)) << 4);
        CP_ASYNC16(so, B + (size_t)(n0 + row) * HH + k0 + ck * 8);
    }
}

__global__ void __launch_bounds__(256, 2)
joint_gemm(const __half* __restrict__ A,
           const __half* __restrict__ B,
           const float* __restrict__ b2,
           float* __restrict__ out)
{
    extern __shared__ __align__(1024) char smem[];
    const uint32_t sb = smem_u32(smem);

    const int tid  = threadIdx.x;
    const int lane = tid & 31;
    const int wid  = tid >> 5;
    const int wm   = wid & 1;          // 0..1 -> 64-row stripes
    const int wn   = wid >> 1;         // 0..3 -> 32-col stripes
    const int n0   = blockIdx.x * BN;
    const int m0   = blockIdx.y * BM;

    const int lml = lane & 15;
    const int lmh = lane >> 4;

    float acc[4][4][4];
    #pragma unroll
    for (int a = 0; a < 4; a++)
        #pragma unroll
        for (int n = 0; n < 4; n++)
            #pragma unroll
            for (int i = 0; i < 4; i++) acc[a][n][i] = 0.0f;

    // prologue: stages 0 and 1
    load_buf(sb,              A, B, m0, n0, 0);
    CP_COMMIT();
    load_buf(sb + STG_STRIDE, A, B, m0, n0, BK);
    CP_COMMIT();
    CP_WAIT1();            // stage 0 complete
    __syncthreads();

    for (int c = 0; c < KITERS; c++) {
        const uint32_t sbuf = sb + (uint32_t)(c % STAGES) * STG_STRIDE;

        // issue loads for stage c+2 into the free slot ((c-1) % STAGES)
        if (c + 2 < KITERS) {
            load_buf(sb + (uint32_t)((c + 2) % STAGES) * STG_STRIDE,
                     A, B, m0, n0, (c + 2) * BK);
            CP_COMMIT();
        }

        // compute stage c
        #pragma unroll
        for (int ks = 0; ks < 4; ks++) {
            const int ck = 2 * ks + lmh;

            uint32_t af[4][4];
            #pragma unroll
            for (int a = 0; a < 4; a++) {
                uint32_t row = (uint32_t)(wm * 64 + a * 16 + lml);
                LDSM4(af[a][0], af[a][1], af[a][2], af[a][3],
                      sbuf + row * 128 + (uint32_t)((ck ^ (row & 7)) << 4));
            }
            uint32_t bf[2][4];
            #pragma unroll
            for (int p = 0; p < 2; p++) {
                uint32_t row = (uint32_t)(wn * 32 + p * 16 + lml);
                LDSM4(bf[p][0], bf[p][1], bf[p][2], bf[p][3],
                      sbuf + 16384u + row * 128 +
                      (uint32_t)((ck ^ (row & 7)) << 4));
            }
            #pragma unroll
            for (int a = 0; a < 4; a++)
                #pragma unroll
                for (int n = 0; n < 4; n++) {
                    int p = n >> 1, s = n & 1;
                    MMA16816(acc[a][n], af[a], bf[p][s], bf[p][s + 2]);
                }
        }

        // wait for next stage, release the one just consumed
        if (c + 2 < KITERS) CP_WAIT1();
        else                CP_WAIT0();
        __syncthreads();
    }

    // epilogue: +b2, direct stores
    #pragma unroll
    for (int n = 0; n < 4; n++) {
        const int col = n0 + wn * 32 + n * 8 + (lane & 3) * 2;
        const float2 bb = *(const float2*)&b2[col];
        #pragma unroll
        for (int a = 0; a < 4; a++) {
            const size_t r0 = (size_t)m0 + wm * 64 + a * 16 + (lane >> 2);
            float2 o0 = { acc[a][n][0] + bb.x, acc[a][n][1] + bb.y };
            float2 o1 = { acc[a][n][2] + bb.x, acc[a][n][3] + bb.y };
            *(float2*)&out[r0 * VV + col]       = o0;
            *(float2*)&out[(r0 + 8) * VV + col] = o1;
        }
    }
}

// ---------------------------------------------------------------------------
// Launch
// ---------------------------------------------------------------------------
extern "C" void kernel_launch(void* const* d_in, const int* in_sizes, int n_in,
                              void* d_out, int out_size)
{
    const float* enc = (const float*)d_in[0];
    const float* dec = (const float*)d_in[1];
    const float* W1  = (const float*)d_in[2];
    const float* b1  = (const float*)d_in[3];
    const float* W2  = (const float*)d_in[4];
    const float* b2  = (const float*)d_in[5];
    float* out = (float*)d_out;

    float *pe = nullptr, *pd = nullptr;
    __half *ga = nullptr, *gb = nullptr;
    cudaGetSymbolAddress((void**)&pe, g_proj_e);
    cudaGetSymbolAddress((void**)&pd, g_proj_d);
    cudaGetSymbolAddress((void**)&ga, g_A);
    cudaGetSymbolAddress((void**)&gb, g_B);

    cudaFuncSetAttribute(joint_gemm,
                         cudaFuncAttributeMaxDynamicSharedMemorySize, SMEM_TOTAL);

    proj_both<<<dim3(HH / 64, 15), 256>>>(enc, dec, W1, b1, pe, pd);
    prep_w2<<<dim3(VV / 32, HH / 32), 256>>>(W2, gb);
    prep_a<<<(MTOT * 160) / 256, 256>>>(ga);

    // grid.x = n-blocks (fastest) -> CTAs sharing an A stripe co-run
    joint_gemm<<<dim3(VV / BN, MTOT / BM), 256, SMEM_TOTAL>>>(ga, gb, b2, out);
}